// round 2
// baseline (speedup 1.0000x reference)
#include <cuda_runtime.h>
#include <cuda_bf16.h>
#include <math.h>

// Problem constants
#define B 8
#define CIN 128
#define D2 256
#define HH 128
#define WW 128
#define NPIX (HH*WW)          // 16384
#define HEADS 8
#define CH 32                  // D2/HEADS
#define NCHUNK 16
#define CHUNKLEN (NPIX/NCHUNK) // 1024

// ---------------- scratch (device globals; no allocation) ----------------
__device__ float g_t[3ull*B*D2*NPIX];     // conv1x1 outputs (pre-depthwise)
__device__ float g_qkv[3ull*B*D2*NPIX];   // post-depthwise q,k,v
__device__ float g_Sp[64*NCHUNK*1024];    // gram partials  [bh][chunk][32*32]
__device__ float g_np[64*NCHUNK*64];      // norm partials  [bh][chunk][64] (32 q + 32 k)
__device__ float g_M[B*128*D2];           // folded projection weights [b][128][256]

// ---------------- generic SGEMM with bias: C = A(MxK) @ B(KxN) + bias ----
// BM=BN=128, BK=8, 256 threads, 8x8 micro-tile per thread.
#define BM 128
#define BN 128
#define BKg 8
__global__ __launch_bounds__(256, 2)
void sgemm_bias(const float* __restrict__ A, long sA,
                const float* __restrict__ Bp, long sB,
                float* __restrict__ C, long sC,
                const float* __restrict__ bias,
                int M, int K, int N)
{
    A  += (long)blockIdx.z * sA;
    Bp += (long)blockIdx.z * sB;
    C  += (long)blockIdx.z * sC;

    const int m0 = blockIdx.y * BM;
    const int n0 = blockIdx.x * BN;

    __shared__ float As[BKg][BM];
    __shared__ float Bs[BKg][BN];

    const int tid = threadIdx.x;
    const int tx = tid & 15;   // 0..15  -> n
    const int ty = tid >> 4;   // 0..15  -> m

    float acc[8][8];
#pragma unroll
    for (int i = 0; i < 8; i++)
#pragma unroll
        for (int j = 0; j < 8; j++) acc[i][j] = 0.f;

    for (int k0 = 0; k0 < K; k0 += BKg) {
        // A tile: 128 rows x 8 k  (transposed into As[k][m])
        {
            int r  = tid >> 1;
            int c4 = (tid & 1) * 4;
            float4 v = *reinterpret_cast<const float4*>(A + (long)(m0 + r) * K + k0 + c4);
            As[c4 + 0][r] = v.x;
            As[c4 + 1][r] = v.y;
            As[c4 + 2][r] = v.z;
            As[c4 + 3][r] = v.w;
        }
        // B tile: 8 k x 128 n
        {
            int r  = tid >> 5;
            int c4 = (tid & 31) * 4;
            float4 v = *reinterpret_cast<const float4*>(Bp + (long)(k0 + r) * N + n0 + c4);
            *reinterpret_cast<float4*>(&Bs[r][c4]) = v;
        }
        __syncthreads();

#pragma unroll
        for (int kk = 0; kk < BKg; kk++) {
            float ar[8], br[8];
            float4 a0 = *reinterpret_cast<const float4*>(&As[kk][ty * 8]);
            float4 a1 = *reinterpret_cast<const float4*>(&As[kk][ty * 8 + 4]);
            float4 b0 = *reinterpret_cast<const float4*>(&Bs[kk][tx * 8]);
            float4 b1 = *reinterpret_cast<const float4*>(&Bs[kk][tx * 8 + 4]);
            ar[0]=a0.x; ar[1]=a0.y; ar[2]=a0.z; ar[3]=a0.w;
            ar[4]=a1.x; ar[5]=a1.y; ar[6]=a1.z; ar[7]=a1.w;
            br[0]=b0.x; br[1]=b0.y; br[2]=b0.z; br[3]=b0.w;
            br[4]=b1.x; br[5]=b1.y; br[6]=b1.z; br[7]=b1.w;
#pragma unroll
            for (int i = 0; i < 8; i++)
#pragma unroll
                for (int j = 0; j < 8; j++)
                    acc[i][j] = fmaf(ar[i], br[j], acc[i][j]);
        }
        __syncthreads();
    }

#pragma unroll
    for (int i = 0; i < 8; i++) {
        float bv = bias[m0 + ty * 8 + i];
        float4 o0, o1;
        o0.x = acc[i][0] + bv; o0.y = acc[i][1] + bv;
        o0.z = acc[i][2] + bv; o0.w = acc[i][3] + bv;
        o1.x = acc[i][4] + bv; o1.y = acc[i][5] + bv;
        o1.z = acc[i][6] + bv; o1.w = acc[i][7] + bv;
        float* cp = C + (long)(m0 + ty * 8 + i) * N + n0 + tx * 8;
        *reinterpret_cast<float4*>(cp)     = o0;
        *reinterpret_cast<float4*>(cp + 4) = o1;
    }
}

// ---------------- depthwise 3x3 SAME, zero pad ----------------
// grid: x=W/32, y=H/8, z=B*D2 (z = b*256 + oc); block (32,8)
__global__ void dwconv3x3(const float* __restrict__ in,
                          const float* __restrict__ w,
                          const float* __restrict__ bias,
                          float* __restrict__ out)
{
    const int zc = blockIdx.z;           // b*256 + oc  -> channel-plane index
    const int oc = zc & (D2 - 1);
    const float* ip = in + (long)zc * NPIX;

    float w9[9];
#pragma unroll
    for (int t = 0; t < 9; t++) w9[t] = w[oc * 9 + t];
    const float bv = bias[oc];

    __shared__ float sm[10][34];
    const int h0 = blockIdx.y * 8;
    const int w0 = blockIdx.x * 32;
    const int tx = threadIdx.x, ty = threadIdx.y;
    const int tid = ty * 32 + tx;

    for (int i = tid; i < 340; i += 256) {
        int r = i / 34, c = i % 34;
        int gh = h0 + r - 1, gw = w0 + c - 1;
        sm[r][c] = (gh >= 0 && gh < HH && gw >= 0 && gw < WW) ? ip[gh * WW + gw] : 0.f;
    }
    __syncthreads();

    float acc = bv;
#pragma unroll
    for (int dy = 0; dy < 3; dy++)
#pragma unroll
        for (int dx = 0; dx < 3; dx++)
            acc = fmaf(sm[ty + dy][tx + dx], w9[dy * 3 + dx], acc);

    out[(long)zc * NPIX + (h0 + ty) * WW + (w0 + tx)] = acc;
}

// ---------------- Gram partials + norm partials ----------------
// grid: (NCHUNK, 64)  block: 128
// q rows for bh are contiguous: base = bh*32*NPIX (since [b][256][n], bh=b*8+h)
__global__ void gram_partial(const float* __restrict__ qg,
                             const float* __restrict__ kg,
                             float* __restrict__ Sp,
                             float* __restrict__ np)
{
    const int bh = blockIdx.y;
    const int chunk = blockIdx.x;
    const float* qb = qg + (long)bh * CH * NPIX + chunk * CHUNKLEN;
    const float* kb = kg + (long)bh * CH * NPIX + chunk * CHUNKLEN;

    __shared__ float qs[32][65];
    __shared__ float ks[32][65];
    const int tid = threadIdx.x;

    // ---- norm partials (64 rows x this chunk), 2 threads per row ----
    {
        __shared__ float sn[128];
        int r = tid >> 1, half = tid & 1;
        const float* p = (r < 32) ? (qb + (long)r * NPIX) : (kb + (long)(r - 32) * NPIX);
        p += half * (CHUNKLEN / 2);
        float s = 0.f;
        for (int i = 0; i < CHUNKLEN / 2; i += 4) {
            float4 v = *reinterpret_cast<const float4*>(p + i);
            s += v.x * v.x + v.y * v.y + v.z * v.z + v.w * v.w;
        }
        sn[tid] = s;
        __syncthreads();
        if (tid < 64) np[((long)bh * NCHUNK + chunk) * 64 + tid] = sn[2 * tid] + sn[2 * tid + 1];
        __syncthreads();
    }

    // ---- gram: 32x32 over this 1024-chunk, tiles of 64 along n ----
    const int c2 = tid >> 3;     // 0..15 -> handles rows 2*c2, 2*c2+1 of q
    const int d4 = tid & 7;      // 0..7  -> handles k rows d4*4 .. d4*4+3
    float acc[2][4];
#pragma unroll
    for (int r = 0; r < 2; r++)
#pragma unroll
        for (int i = 0; i < 4; i++) acc[r][i] = 0.f;

    for (int t0 = 0; t0 < CHUNKLEN; t0 += 64) {
        // load 32x64 q and k tiles: 512 float4s each side, 128 threads -> 4 reps,
        // each rep loads one float4 of q AND one of k.
#pragma unroll
        for (int rep = 0; rep < 4; rep++) {
            int lin4 = rep * 128 + tid;         // 0..511
            int row = lin4 >> 4;                // 0..31
            int col = (lin4 & 15) * 4;          // 0..60
            float4 v = *reinterpret_cast<const float4*>(qb + (long)row * NPIX + t0 + col);
            qs[row][col] = v.x; qs[row][col+1] = v.y; qs[row][col+2] = v.z; qs[row][col+3] = v.w;
            float4 u = *reinterpret_cast<const float4*>(kb + (long)row * NPIX + t0 + col);
            ks[row][col] = u.x; ks[row][col+1] = u.y; ks[row][col+2] = u.z; ks[row][col+3] = u.w;
        }
        __syncthreads();

#pragma unroll 8
        for (int nn = 0; nn < 64; nn++) {
            float q0 = qs[2 * c2][nn];
            float q1 = qs[2 * c2 + 1][nn];
#pragma unroll
            for (int i = 0; i < 4; i++) {
                float kv = ks[d4 * 4 + i][nn];
                acc[0][i] = fmaf(q0, kv, acc[0][i]);
                acc[1][i] = fmaf(q1, kv, acc[1][i]);
            }
        }
        __syncthreads();
    }

    float* sp = Sp + ((long)bh * NCHUNK + chunk) * 1024;
#pragma unroll
    for (int r = 0; r < 2; r++)
#pragma unroll
        for (int i = 0; i < 4; i++)
            sp[(2 * c2 + r) * 32 + (d4 * 4 + i)] = acc[r][i];
}

// ---------------- reduce + softmax + fold attention into projection ----
// grid: 64 (bh), block: 128
__global__ void softmax_fold(const float* __restrict__ Sp,
                             const float* __restrict__ np,
                             const float* __restrict__ P,   // pw [128][256]
                             float* __restrict__ Mout)      // [b][128][256]
{
    const int bh = blockIdx.x;
    const int b  = bh >> 3;
    const int hh = bh & 7;
    const int tid = threadIdx.x;

    __shared__ float sS[1024];
    __shared__ float qn[32], kn[32];

    for (int e = tid; e < 1024; e += 128) {
        float s = 0.f;
        for (int j = 0; j < NCHUNK; j++) s += Sp[((long)bh * NCHUNK + j) * 1024 + e];
        sS[e] = s;
    }
    if (tid < 64) {
        float s = 0.f;
        for (int j = 0; j < NCHUNK; j++) s += np[((long)bh * NCHUNK + j) * 64 + tid];
        float nv = fmaxf(sqrtf(s), 1e-12f);
        if (tid < 32) qn[tid] = nv; else kn[tid - 32] = nv;
    }
    __syncthreads();

    const float scale = 0.25f;   // 1/sqrt(128/8)
    if (tid < 32) {
        const int c = tid;
        float inv_q = 1.f / qn[c];
        float vals[32];
        float mx = -1e30f;
#pragma unroll
        for (int d = 0; d < 32; d++) {
            float v = sS[c * 32 + d] * scale * inv_q / kn[d];
            vals[d] = v;
            mx = fmaxf(mx, v);
        }
        float sum = 0.f;
#pragma unroll
        for (int d = 0; d < 32; d++) { vals[d] = expf(vals[d] - mx); sum += vals[d]; }
        float inv = 1.f / sum;
#pragma unroll
        for (int d = 0; d < 32; d++) sS[c * 32 + d] = vals[d] * inv;
    }
    __syncthreads();

    // M[b][r][hh*32+d] = sum_c P[r][hh*32+c] * A[c][d]
    float prow[32];
#pragma unroll
    for (int c = 0; c < 32; c++) prow[c] = P[tid * D2 + hh * 32 + c];
#pragma unroll 4
    for (int d = 0; d < 32; d++) {
        float a = 0.f;
#pragma unroll
        for (int c = 0; c < 32; c++) a = fmaf(prow[c], sS[c * 32 + d], a);
        Mout[((long)b * 128 + tid) * D2 + hh * 32 + d] = a;
    }
}

// ---------------- launch ----------------
extern "C" void kernel_launch(void* const* d_in, const int* in_sizes, int n_in,
                              void* d_out, int out_size)
{
    const float* x[3]  = { (const float*)d_in[0], (const float*)d_in[1], (const float*)d_in[2] };
    const float* w1[3] = { (const float*)d_in[3], (const float*)d_in[5], (const float*)d_in[7] };
    const float* b1[3] = { (const float*)d_in[4], (const float*)d_in[6], (const float*)d_in[8] };
    const float* wd[3] = { (const float*)d_in[9], (const float*)d_in[11], (const float*)d_in[13] };
    const float* bd[3] = { (const float*)d_in[10], (const float*)d_in[12], (const float*)d_in[14] };
    const float* pw = (const float*)d_in[15];
    const float* pb = (const float*)d_in[16];
    float* out = (float*)d_out;

    float *t_ptr, *qkv_ptr, *Sp_ptr, *np_ptr, *M_ptr;
    cudaGetSymbolAddress((void**)&t_ptr,   g_t);
    cudaGetSymbolAddress((void**)&qkv_ptr, g_qkv);
    cudaGetSymbolAddress((void**)&Sp_ptr,  g_Sp);
    cudaGetSymbolAddress((void**)&np_ptr,  g_np);
    cudaGetSymbolAddress((void**)&M_ptr,   g_M);

    const long planeStride = (long)D2 * NPIX;        // per-batch stride of t/qkv
    const long streamStride = (long)B * planeStride; // per-stream stride

    // 1) three pointwise convs as batched SGEMM: [256x128] @ [128x16384]
    {
        dim3 grid(NPIX / BN, D2 / BM, B);
        for (int s = 0; s < 3; s++) {
            sgemm_bias<<<grid, 256>>>(w1[s], 0,
                                      x[s], (long)CIN * NPIX,
                                      t_ptr + s * streamStride, planeStride,
                                      b1[s], D2, CIN, NPIX);
        }
    }
    // 2) depthwise 3x3
    {
        dim3 grid(WW / 32, HH / 8, B * D2);
        dim3 blk(32, 8);
        for (int s = 0; s < 3; s++) {
            dwconv3x3<<<grid, blk>>>(t_ptr + s * streamStride, wd[s], bd[s],
                                     qkv_ptr + s * streamStride);
        }
    }
    // 3) gram partials (q = stream0, k = stream1)
    {
        dim3 grid(NCHUNK, 64);
        gram_partial<<<grid, 128>>>(qkv_ptr + 0 * streamStride,
                                    qkv_ptr + 1 * streamStride,
                                    Sp_ptr, np_ptr);
    }
    // 4) softmax + fold attention into projection weights
    softmax_fold<<<64, 128>>>(Sp_ptr, np_ptr, pw, M_ptr);

    // 5) final: out[b] = M[b](128x256) @ v[b](256x16384) + pb
    {
        dim3 grid(NPIX / BN, 128 / BM, B);
        sgemm_bias<<<grid, 256>>>(M_ptr, (long)128 * D2,
                                  qkv_ptr + 2 * streamStride, planeStride,
                                  out, (long)CIN * NPIX,
                                  pb, 128, D2, NPIX);
    }
}

// round 3
// speedup vs baseline: 1.6346x; 1.6346x over previous
#include <cuda_runtime.h>
#include <cuda_bf16.h>
#include <math.h>

// Problem constants
#define B 8
#define CIN 128
#define D2 256
#define HH 128
#define WW 128
#define NPIX (HH*WW)          // 16384
#define HEADS 8
#define CH 32                  // D2/HEADS
#define NCHUNK 16
#define CHUNKLEN (NPIX/NCHUNK) // 1024

// ---------------- scratch (device globals; no allocation) ----------------
__device__ float g_t[3ull*B*D2*NPIX];     // conv1x1 outputs (pre-depthwise)
__device__ float g_qkv[3ull*B*D2*NPIX];   // post-depthwise q,k,v
__device__ float g_Sp[64*NCHUNK*1024];    // gram partials  [bh][chunk][32*32]
__device__ float g_np[64*NCHUNK*64];      // norm partials  [bh][chunk][64]
__device__ float g_M[B*128*D2];           // folded projection weights [b][128][256]

// =====================================================================
// tf32 tensor-core GEMM with bias: C = A(MxK) @ B(KxN) + bias[m]
// Block tile 128x128, K-tile 32, 256 threads (8 warps as 2x4 of 64x32).
// A row-major, B row-major. mma.sync m16n8k8 tf32.
// =====================================================================
#define GK 32
__global__ __launch_bounds__(256)
void gemm_tf32_bias(const float* __restrict__ A, long sA,
                    const float* __restrict__ Bm, long sB,
                    float* __restrict__ C, long sC,
                    const float* __restrict__ bias,
                    int M, int K, int N)
{
    A  += (long)blockIdx.z * sA;
    Bm += (long)blockIdx.z * sB;
    C  += (long)blockIdx.z * sC;

    const int m0 = blockIdx.y * 128;
    const int n0 = blockIdx.x * 128;

    __shared__ float As[128][36];   // [m][k], stride 36 -> bank = (4m+k)&31
    __shared__ float Bs[GK][136];   // [k][n], stride 136 -> bank = (8k+n)&31

    const int tid  = threadIdx.x;
    const int wid  = tid >> 5;
    const int lane = tid & 31;
    const int wm0 = (wid >> 2) * 64;   // warp m offset in tile
    const int wn0 = (wid & 3) * 32;    // warp n offset in tile
    const int r = lane >> 2;           // groupID 0..7
    const int c = lane & 3;            // threadID in group 0..3

    float acc[4][4][4];
#pragma unroll
    for (int mt = 0; mt < 4; mt++)
#pragma unroll
        for (int nt = 0; nt < 4; nt++)
#pragma unroll
            for (int i = 0; i < 4; i++) acc[mt][nt][i] = 0.f;

    for (int k0 = 0; k0 < K; k0 += GK) {
        // load A tile: 128 rows x 32 k = 1024 float4
#pragma unroll
        for (int it = 0; it < 4; it++) {
            int lin = it * 256 + tid;
            int row = lin >> 3;
            int c4  = (lin & 7) * 4;
            float4 v = *reinterpret_cast<const float4*>(A + (long)(m0 + row) * K + k0 + c4);
            *reinterpret_cast<float4*>(&As[row][c4]) = v;
        }
        // load B tile: 32 k x 128 n = 1024 float4
#pragma unroll
        for (int it = 0; it < 4; it++) {
            int lin = it * 256 + tid;
            int row = lin >> 5;
            int c4  = (lin & 31) * 4;
            float4 v = *reinterpret_cast<const float4*>(Bm + (long)(k0 + row) * N + n0 + c4);
            *reinterpret_cast<float4*>(&Bs[row][c4]) = v;
        }
        __syncthreads();

#pragma unroll
        for (int ks = 0; ks < GK; ks += 8) {
            unsigned af[4][4], bf[4][2];
#pragma unroll
            for (int mt = 0; mt < 4; mt++) {
                int mr = wm0 + mt * 16 + r;
                af[mt][0] = __float_as_uint(As[mr    ][ks + c    ]);
                af[mt][1] = __float_as_uint(As[mr + 8][ks + c    ]);
                af[mt][2] = __float_as_uint(As[mr    ][ks + c + 4]);
                af[mt][3] = __float_as_uint(As[mr + 8][ks + c + 4]);
            }
#pragma unroll
            for (int nt = 0; nt < 4; nt++) {
                int nc = wn0 + nt * 8 + r;
                bf[nt][0] = __float_as_uint(Bs[ks + c    ][nc]);
                bf[nt][1] = __float_as_uint(Bs[ks + c + 4][nc]);
            }
#pragma unroll
            for (int mt = 0; mt < 4; mt++)
#pragma unroll
                for (int nt = 0; nt < 4; nt++) {
                    asm volatile(
                        "mma.sync.aligned.m16n8k8.row.col.f32.tf32.tf32.f32 "
                        "{%0,%1,%2,%3}, {%4,%5,%6,%7}, {%8,%9}, {%0,%1,%2,%3};\n"
                        : "+f"(acc[mt][nt][0]), "+f"(acc[mt][nt][1]),
                          "+f"(acc[mt][nt][2]), "+f"(acc[mt][nt][3])
                        : "r"(af[mt][0]), "r"(af[mt][1]), "r"(af[mt][2]), "r"(af[mt][3]),
                          "r"(bf[nt][0]), "r"(bf[nt][1]));
                }
        }
        __syncthreads();
    }

    // epilogue: c0:(r,2c) c1:(r,2c+1) c2:(r+8,2c) c3:(r+8,2c+1)
#pragma unroll
    for (int mt = 0; mt < 4; mt++) {
        int row0 = m0 + wm0 + mt * 16 + r;
        float bv0 = bias[row0];
        float bv8 = bias[row0 + 8];
#pragma unroll
        for (int nt = 0; nt < 4; nt++) {
            int col = n0 + wn0 + nt * 8 + 2 * c;
            float2 v0 = { acc[mt][nt][0] + bv0, acc[mt][nt][1] + bv0 };
            float2 v8 = { acc[mt][nt][2] + bv8, acc[mt][nt][3] + bv8 };
            *reinterpret_cast<float2*>(C + (long)row0 * N + col)       = v0;
            *reinterpret_cast<float2*>(C + (long)(row0 + 8) * N + col) = v8;
        }
    }
}

// =====================================================================
// depthwise 3x3 SAME, zero pad — 64x16 tile, 4 outputs/thread,
// one launch covers all 3 streams (scratch is contiguous).
// grid: x=WW/64, y=HH/16, z=3*B*D2 ; block 256
// =====================================================================
__global__ __launch_bounds__(256)
void dwconv3x3_v2(const float* __restrict__ in,
                  float* __restrict__ out,
                  const float* __restrict__ w0, const float* __restrict__ b0,
                  const float* __restrict__ w1, const float* __restrict__ b1,
                  const float* __restrict__ w2, const float* __restrict__ b2)
{
    const int z = blockIdx.z;                 // s*2048 + b*256 + oc
    const int s = z >> 11;
    const int oc = z & (D2 - 1);
    const float* wsel = (s == 0) ? w0 : (s == 1) ? w1 : w2;
    const float* bsel = (s == 0) ? b0 : (s == 1) ? b1 : b2;

    float w9[9];
#pragma unroll
    for (int t = 0; t < 9; t++) w9[t] = wsel[oc * 9 + t];
    const float bv = bsel[oc];

    const float* ip = in + (long)z * NPIX;
    float* op = out + (long)z * NPIX;

    __shared__ float sm[18][66];

    const int h0 = blockIdx.y * 16;
    const int w0p = blockIdx.x * 64;
    const int tx  = threadIdx.x & 63;   // 0..63
    const int tyq = threadIdx.x >> 6;   // 0..3

    // halo load: rows h0-1 .. h0+16, cols w0p-1 .. w0p+64
    for (int rr = tyq; rr < 18; rr += 4) {
        int gh = h0 + rr - 1;
        bool hok = (gh >= 0) && (gh < HH);
        {
            int gw = w0p + tx - 1;
            sm[rr][tx] = (hok && gw >= 0 && gw < WW) ? ip[gh * WW + gw] : 0.f;
        }
        if (tx < 2) {
            int gw = w0p + 63 + tx;
            sm[rr][64 + tx] = (hok && gw < WW) ? ip[gh * WW + gw] : 0.f;
        }
    }
    __syncthreads();

    // rolling 3-row window in registers
    int rbase = tyq * 4;     // output rows rbase..rbase+3 (smem rows rbase..rbase+5)
    float c0[3], c1[3], c2[3];
#pragma unroll
    for (int j = 0; j < 3; j++) {
        c0[j] = sm[rbase    ][tx + j];
        c1[j] = sm[rbase + 1][tx + j];
        c2[j] = sm[rbase + 2][tx + j];
    }
#pragma unroll
    for (int i = 0; i < 4; i++) {
        float a = bv;
#pragma unroll
        for (int j = 0; j < 3; j++) {
            a = fmaf(c0[j], w9[j], a);
            a = fmaf(c1[j], w9[3 + j], a);
            a = fmaf(c2[j], w9[6 + j], a);
        }
        op[(h0 + rbase + i) * WW + w0p + tx] = a;
        if (i < 3) {
#pragma unroll
            for (int j = 0; j < 3; j++) {
                c0[j] = c1[j]; c1[j] = c2[j];
                c2[j] = sm[rbase + 3 + i][tx + j];
            }
        }
    }
}

// ---------------- Gram partials + norm partials ----------------
// grid: (NCHUNK, 64)  block: 128
__global__ void gram_partial(const float* __restrict__ qg,
                             const float* __restrict__ kg,
                             float* __restrict__ Sp,
                             float* __restrict__ np)
{
    const int bh = blockIdx.y;
    const int chunk = blockIdx.x;
    const float* qb = qg + (long)bh * CH * NPIX + chunk * CHUNKLEN;
    const float* kb = kg + (long)bh * CH * NPIX + chunk * CHUNKLEN;

    __shared__ float qs[32][65];
    __shared__ float ks[32][65];
    const int tid = threadIdx.x;

    // ---- norm partials ----
    {
        __shared__ float sn[128];
        int r = tid >> 1, half = tid & 1;
        const float* p = (r < 32) ? (qb + (long)r * NPIX) : (kb + (long)(r - 32) * NPIX);
        p += half * (CHUNKLEN / 2);
        float s = 0.f;
        for (int i = 0; i < CHUNKLEN / 2; i += 4) {
            float4 v = *reinterpret_cast<const float4*>(p + i);
            s += v.x * v.x + v.y * v.y + v.z * v.z + v.w * v.w;
        }
        sn[tid] = s;
        __syncthreads();
        if (tid < 64) np[((long)bh * NCHUNK + chunk) * 64 + tid] = sn[2 * tid] + sn[2 * tid + 1];
        __syncthreads();
    }

    // ---- gram ----
    const int c2 = tid >> 3;
    const int d4 = tid & 7;
    float acc[2][4];
#pragma unroll
    for (int r = 0; r < 2; r++)
#pragma unroll
        for (int i = 0; i < 4; i++) acc[r][i] = 0.f;

    for (int t0 = 0; t0 < CHUNKLEN; t0 += 64) {
#pragma unroll
        for (int rep = 0; rep < 4; rep++) {
            int lin4 = rep * 128 + tid;
            int row = lin4 >> 4;
            int col = (lin4 & 15) * 4;
            float4 v = *reinterpret_cast<const float4*>(qb + (long)row * NPIX + t0 + col);
            qs[row][col] = v.x; qs[row][col+1] = v.y; qs[row][col+2] = v.z; qs[row][col+3] = v.w;
            float4 u = *reinterpret_cast<const float4*>(kb + (long)row * NPIX + t0 + col);
            ks[row][col] = u.x; ks[row][col+1] = u.y; ks[row][col+2] = u.z; ks[row][col+3] = u.w;
        }
        __syncthreads();

#pragma unroll 8
        for (int nn = 0; nn < 64; nn++) {
            float q0 = qs[2 * c2][nn];
            float q1 = qs[2 * c2 + 1][nn];
#pragma unroll
            for (int i = 0; i < 4; i++) {
                float kv = ks[d4 * 4 + i][nn];
                acc[0][i] = fmaf(q0, kv, acc[0][i]);
                acc[1][i] = fmaf(q1, kv, acc[1][i]);
            }
        }
        __syncthreads();
    }

    float* sp = Sp + ((long)bh * NCHUNK + chunk) * 1024;
#pragma unroll
    for (int r = 0; r < 2; r++)
#pragma unroll
        for (int i = 0; i < 4; i++)
            sp[(2 * c2 + r) * 32 + (d4 * 4 + i)] = acc[r][i];
}

// ---------------- reduce + softmax + fold attention into projection ----
__global__ void softmax_fold(const float* __restrict__ Sp,
                             const float* __restrict__ np,
                             const float* __restrict__ P,
                             float* __restrict__ Mout)
{
    const int bh = blockIdx.x;
    const int b  = bh >> 3;
    const int hh = bh & 7;
    const int tid = threadIdx.x;

    __shared__ float sS[1024];
    __shared__ float qn[32], kn[32];

    for (int e = tid; e < 1024; e += 128) {
        float s = 0.f;
        for (int j = 0; j < NCHUNK; j++) s += Sp[((long)bh * NCHUNK + j) * 1024 + e];
        sS[e] = s;
    }
    if (tid < 64) {
        float s = 0.f;
        for (int j = 0; j < NCHUNK; j++) s += np[((long)bh * NCHUNK + j) * 64 + tid];
        float nv = fmaxf(sqrtf(s), 1e-12f);
        if (tid < 32) qn[tid] = nv; else kn[tid - 32] = nv;
    }
    __syncthreads();

    const float scale = 0.25f;
    if (tid < 32) {
        const int c = tid;
        float inv_q = 1.f / qn[c];
        float vals[32];
        float mx = -1e30f;
#pragma unroll
        for (int d = 0; d < 32; d++) {
            float v = sS[c * 32 + d] * scale * inv_q / kn[d];
            vals[d] = v;
            mx = fmaxf(mx, v);
        }
        float sum = 0.f;
#pragma unroll
        for (int d = 0; d < 32; d++) { vals[d] = expf(vals[d] - mx); sum += vals[d]; }
        float inv = 1.f / sum;
#pragma unroll
        for (int d = 0; d < 32; d++) sS[c * 32 + d] = vals[d] * inv;
    }
    __syncthreads();

    float prow[32];
#pragma unroll
    for (int c = 0; c < 32; c++) prow[c] = P[tid * D2 + hh * 32 + c];
#pragma unroll 4
    for (int d = 0; d < 32; d++) {
        float a = 0.f;
#pragma unroll
        for (int c = 0; c < 32; c++) a = fmaf(prow[c], sS[c * 32 + d], a);
        Mout[((long)b * 128 + tid) * D2 + hh * 32 + d] = a;
    }
}

// ---------------- launch ----------------
extern "C" void kernel_launch(void* const* d_in, const int* in_sizes, int n_in,
                              void* d_out, int out_size)
{
    const float* x[3]  = { (const float*)d_in[0], (const float*)d_in[1], (const float*)d_in[2] };
    const float* w1[3] = { (const float*)d_in[3], (const float*)d_in[5], (const float*)d_in[7] };
    const float* b1[3] = { (const float*)d_in[4], (const float*)d_in[6], (const float*)d_in[8] };
    const float* wd[3] = { (const float*)d_in[9], (const float*)d_in[11], (const float*)d_in[13] };
    const float* bd[3] = { (const float*)d_in[10], (const float*)d_in[12], (const float*)d_in[14] };
    const float* pw = (const float*)d_in[15];
    const float* pb = (const float*)d_in[16];
    float* out = (float*)d_out;

    float *t_ptr, *qkv_ptr, *Sp_ptr, *np_ptr, *M_ptr;
    cudaGetSymbolAddress((void**)&t_ptr,   g_t);
    cudaGetSymbolAddress((void**)&qkv_ptr, g_qkv);
    cudaGetSymbolAddress((void**)&Sp_ptr,  g_Sp);
    cudaGetSymbolAddress((void**)&np_ptr,  g_np);
    cudaGetSymbolAddress((void**)&M_ptr,   g_M);

    const long planeStride = (long)D2 * NPIX;
    const long streamStride = (long)B * planeStride;

    // 1) three pointwise convs: [256x128] @ [128x16384] per batch (tf32)
    {
        dim3 grid(NPIX / 128, D2 / 128, B);
        for (int s = 0; s < 3; s++) {
            gemm_tf32_bias<<<grid, 256>>>(w1[s], 0,
                                          x[s], (long)CIN * NPIX,
                                          t_ptr + s * streamStride, planeStride,
                                          b1[s], D2, CIN, NPIX);
        }
    }
    // 2) depthwise 3x3 — all three streams in one launch
    {
        dim3 grid(WW / 64, HH / 16, 3 * B * D2);
        dwconv3x3_v2<<<grid, 256>>>(t_ptr, qkv_ptr,
                                    wd[0], bd[0], wd[1], bd[1], wd[2], bd[2]);
    }
    // 3) gram partials
    {
        dim3 grid(NCHUNK, 64);
        gram_partial<<<grid, 128>>>(qkv_ptr + 0 * streamStride,
                                    qkv_ptr + 1 * streamStride,
                                    Sp_ptr, np_ptr);
    }
    // 4) softmax + fold
    softmax_fold<<<64, 128>>>(Sp_ptr, np_ptr, pw, M_ptr);

    // 5) final: out[b] = M[b](128x256) @ v[b](256x16384) + pb (tf32)
    {
        dim3 grid(NPIX / 128, 1, B);
        gemm_tf32_bias<<<grid, 256>>>(M_ptr, (long)128 * D2,
                                      qkv_ptr + 2 * streamStride, planeStride,
                                      out, (long)CIN * NPIX,
                                      pb, 128, D2, NPIX);
    }
}

// round 5
// speedup vs baseline: 1.9986x; 1.2227x over previous
#include <cuda_runtime.h>
#include <cuda_bf16.h>
#include <math.h>

// Problem constants
#define B 8
#define CIN 128
#define D2 256
#define HH 128
#define WW 128
#define NPIX (HH*WW)          // 16384
#define HEADS 8
#define CH 32                  // D2/HEADS
#define NCHUNK 16
#define CHUNKLEN (NPIX/NCHUNK) // 1024

// ---------------- scratch (device globals; no allocation) ----------------
__device__ float g_t[3ull*B*D2*NPIX];     // conv1x1 outputs (pre-depthwise)
__device__ float g_qkv[3ull*B*D2*NPIX];   // post-depthwise q,k,v
__device__ float g_Sp[64*NCHUNK*1024];    // gram partials  [bh][chunk][32*32]
__device__ float g_np[64*NCHUNK*64];      // norm partials  [bh][chunk][64]
__device__ float g_M[B*128*D2];           // folded projection weights [b][128][256]

// ---------------- cp.async helpers ----------------
__device__ __forceinline__ unsigned smem_u32(const void* p) {
    unsigned a;
    asm("{ .reg .u64 t; cvta.to.shared.u64 t, %1; cvt.u32.u64 %0, t; }" : "=r"(a) : "l"(p));
    return a;
}
#define CP_ASYNC8(dst, src)  asm volatile("cp.async.ca.shared.global [%0], [%1], 8;\n"  :: "r"(dst), "l"(src))
#define CP_ASYNC16(dst, src) asm volatile("cp.async.cg.shared.global [%0], [%1], 16;\n" :: "r"(dst), "l"(src))
#define CP_COMMIT()          asm volatile("cp.async.commit_group;\n")
#define CP_WAIT1()           asm volatile("cp.async.wait_group 1;\n")
#define CP_WAIT0()           asm volatile("cp.async.wait_group 0;\n")

// =====================================================================
// tf32 tensor-core GEMM with bias, cp.async double-buffered,
// DYNAMIC shared memory (71680 B > 48K static cap).
// C = A(MxK) @ B(KxN) + bias[m]. Block tile 128x128, K-tile 32, 256 thr.
// =====================================================================
#define GK 32
#define AS_STRIDE 36
#define BS_STRIDE 136
#define AS_STAGE (128 * AS_STRIDE)                  // floats per stage
#define BS_STAGE (GK * BS_STRIDE)
#define SMEM_GEMM ((2 * AS_STAGE + 2 * BS_STAGE) * 4)  // 71680 bytes

__global__ __launch_bounds__(256)
void gemm_tf32_bias(const float* __restrict__ A, long sA,
                    const float* __restrict__ Bm, long sB,
                    float* __restrict__ C, long sC,
                    const float* __restrict__ bias,
                    int M, int K, int N)
{
    extern __shared__ float dynsm[];
    float* AsBase = dynsm;                    // [2][128][36]
    float* BsBase = dynsm + 2 * AS_STAGE;     // [2][GK][136]

    A  += (long)blockIdx.z * sA;
    Bm += (long)blockIdx.z * sB;
    C  += (long)blockIdx.z * sC;

    const int m0 = blockIdx.y * 128;
    const int n0 = blockIdx.x * 128;

    const int tid  = threadIdx.x;
    const int wid  = tid >> 5;
    const int lane = tid & 31;
    const int wm0 = (wid >> 2) * 64;
    const int wn0 = (wid & 3) * 32;
    const int r = lane >> 2;
    const int c = lane & 3;

    float acc[4][4][4];
#pragma unroll
    for (int mt = 0; mt < 4; mt++)
#pragma unroll
        for (int nt = 0; nt < 4; nt++)
#pragma unroll
            for (int i = 0; i < 4; i++) acc[mt][nt][i] = 0.f;

    const int nIter = K / GK;

    // async tile issue: A as 8B chunks (2048 per stage), B as 16B chunks (1024)
    auto issue = [&](int t) {
        const int s = t & 1;
        const int k0 = t * GK;
        float* As = AsBase + s * AS_STAGE;
        float* Bs = BsBase + s * BS_STAGE;
        // A: 128 x 32 floats -> 2048 x 8B; 8 per thread
#pragma unroll
        for (int it = 0; it < 8; it++) {
            int lin = it * 256 + tid;
            int row = lin >> 4;
            int c2  = (lin & 15) * 2;
            unsigned dst = smem_u32(As + row * AS_STRIDE + c2);
            CP_ASYNC8(dst, A + (long)(m0 + row) * K + k0 + c2);
        }
        // B: 32 x 128 floats -> 1024 x 16B; 4 per thread
#pragma unroll
        for (int it = 0; it < 4; it++) {
            int lin = it * 256 + tid;
            int row = lin >> 5;
            int c4  = (lin & 31) * 4;
            unsigned dst = smem_u32(Bs + row * BS_STRIDE + c4);
            CP_ASYNC16(dst, Bm + (long)(k0 + row) * N + n0 + c4);
        }
    };

    issue(0);
    CP_COMMIT();

    for (int t = 0; t < nIter; t++) {
        if (t + 1 < nIter) { issue(t + 1); CP_COMMIT(); CP_WAIT1(); }
        else               { CP_WAIT0(); }
        __syncthreads();

        const int s = t & 1;
        const float* As = AsBase + s * AS_STAGE;
        const float* Bs = BsBase + s * BS_STAGE;
#pragma unroll
        for (int ks = 0; ks < GK; ks += 8) {
            unsigned af[4][4], bf[4][2];
#pragma unroll
            for (int mt = 0; mt < 4; mt++) {
                int mr = wm0 + mt * 16 + r;
                af[mt][0] = __float_as_uint(As[(mr    ) * AS_STRIDE + ks + c    ]);
                af[mt][1] = __float_as_uint(As[(mr + 8) * AS_STRIDE + ks + c    ]);
                af[mt][2] = __float_as_uint(As[(mr    ) * AS_STRIDE + ks + c + 4]);
                af[mt][3] = __float_as_uint(As[(mr + 8) * AS_STRIDE + ks + c + 4]);
            }
#pragma unroll
            for (int nt = 0; nt < 4; nt++) {
                int nc = wn0 + nt * 8 + r;
                bf[nt][0] = __float_as_uint(Bs[(ks + c    ) * BS_STRIDE + nc]);
                bf[nt][1] = __float_as_uint(Bs[(ks + c + 4) * BS_STRIDE + nc]);
            }
#pragma unroll
            for (int mt = 0; mt < 4; mt++)
#pragma unroll
                for (int nt = 0; nt < 4; nt++) {
                    asm volatile(
                        "mma.sync.aligned.m16n8k8.row.col.f32.tf32.tf32.f32 "
                        "{%0,%1,%2,%3}, {%4,%5,%6,%7}, {%8,%9}, {%0,%1,%2,%3};\n"
                        : "+f"(acc[mt][nt][0]), "+f"(acc[mt][nt][1]),
                          "+f"(acc[mt][nt][2]), "+f"(acc[mt][nt][3])
                        : "r"(af[mt][0]), "r"(af[mt][1]), "r"(af[mt][2]), "r"(af[mt][3]),
                          "r"(bf[nt][0]), "r"(bf[nt][1]));
                }
        }
        __syncthreads();
    }

#pragma unroll
    for (int mt = 0; mt < 4; mt++) {
        int row0 = m0 + wm0 + mt * 16 + r;
        float bv0 = bias[row0];
        float bv8 = bias[row0 + 8];
#pragma unroll
        for (int nt = 0; nt < 4; nt++) {
            int col = n0 + wn0 + nt * 8 + 2 * c;
            float2 v0 = { acc[mt][nt][0] + bv0, acc[mt][nt][1] + bv0 };
            float2 v8 = { acc[mt][nt][2] + bv8, acc[mt][nt][3] + bv8 };
            *reinterpret_cast<float2*>(C + (long)row0 * N + col)       = v0;
            *reinterpret_cast<float2*>(C + (long)(row0 + 8) * N + col) = v8;
        }
    }
}

// =====================================================================
// depthwise 3x3 SAME — full-width 128x32 tiles, float4 in/out,
// 4 outputs/thread-iter, conflict-free smem (stride 133).
// grid: (1, HH/32, 3*B*D2); block 256
// =====================================================================
#define DWROWS 32
__global__ __launch_bounds__(256)
void dwconv3x3_v3(const float* __restrict__ in,
                  float* __restrict__ out,
                  const float* __restrict__ w0, const float* __restrict__ b0,
                  const float* __restrict__ w1, const float* __restrict__ b1,
                  const float* __restrict__ w2, const float* __restrict__ b2)
{
    const int z = blockIdx.z;                 // s*2048 + b*256 + oc
    const int s = z >> 11;
    const int oc = z & (D2 - 1);
    const float* wsel = (s == 0) ? w0 : (s == 1) ? w1 : w2;
    const float* bsel = (s == 0) ? b0 : (s == 1) ? b1 : b2;

    float w9[9];
#pragma unroll
    for (int t = 0; t < 9; t++) w9[t] = wsel[oc * 9 + t];
    const float bv = bsel[oc];

    const float* ip = in + (long)z * NPIX;
    float* op = out + (long)z * NPIX;

    // smem rows 0..33 = global rows h0-1 .. h0+32; col j = global col j-1
    __shared__ float sm[34 * 133];

    const int tid = threadIdx.x;
    const int h0 = blockIdx.y * DWROWS;

    // load: 34 rows x 32 float4
    for (int i = tid; i < 34 * 32; i += 256) {
        int row = i >> 5;
        int c4  = i & 31;
        int gh = h0 - 1 + row;
        float4 v = make_float4(0.f, 0.f, 0.f, 0.f);
        if (gh >= 0 && gh < HH)
            v = *reinterpret_cast<const float4*>(ip + gh * WW + c4 * 4);
        float* d = &sm[row * 133 + 1 + c4 * 4];
        d[0] = v.x; d[1] = v.y; d[2] = v.z; d[3] = v.w;
        if (c4 == 0)  sm[row * 133] = 0.f;
        if (c4 == 31) sm[row * 133 + 129] = 0.f;
    }
    __syncthreads();

    const int lane = tid & 31;     // -> row
    const int w    = tid >> 5;     // -> strip base
#pragma unroll
    for (int it = 0; it < 4; it++) {
        const int sc = w + it * 8;          // strip col 0..31 (global cols sc*4..sc*4+3)
        const float* base = sm + lane * 133 + sc * 4;
        float v[3][6];
#pragma unroll
        for (int dy = 0; dy < 3; dy++)
#pragma unroll
            for (int dx = 0; dx < 6; dx++)
                v[dy][dx] = base[dy * 133 + dx];
        float4 o;
        float* po = &o.x;
#pragma unroll
        for (int j = 0; j < 4; j++) {
            float a = bv;
#pragma unroll
            for (int dy = 0; dy < 3; dy++)
#pragma unroll
                for (int dx = 0; dx < 3; dx++)
                    a = fmaf(v[dy][j + dx], w9[dy * 3 + dx], a);
            po[j] = a;
        }
        *reinterpret_cast<float4*>(op + (h0 + lane) * WW + sc * 4) = o;
    }
}

// ---------------- Gram partials + norm partials ----------------
// grid: (NCHUNK, 64)  block: 128
__global__ void gram_partial(const float* __restrict__ qg,
                             const float* __restrict__ kg,
                             float* __restrict__ Sp,
                             float* __restrict__ np)
{
    const int bh = blockIdx.y;
    const int chunk = blockIdx.x;
    const float* qb = qg + (long)bh * CH * NPIX + chunk * CHUNKLEN;
    const float* kb = kg + (long)bh * CH * NPIX + chunk * CHUNKLEN;

    __shared__ float qs[32][65];
    __shared__ float ks[32][65];
    const int tid = threadIdx.x;

    // ---- norm partials ----
    {
        __shared__ float sn[128];
        int r = tid >> 1, half = tid & 1;
        const float* p = (r < 32) ? (qb + (long)r * NPIX) : (kb + (long)(r - 32) * NPIX);
        p += half * (CHUNKLEN / 2);
        float s = 0.f;
        for (int i = 0; i < CHUNKLEN / 2; i += 4) {
            float4 v = *reinterpret_cast<const float4*>(p + i);
            s += v.x * v.x + v.y * v.y + v.z * v.z + v.w * v.w;
        }
        sn[tid] = s;
        __syncthreads();
        if (tid < 64) np[((long)bh * NCHUNK + chunk) * 64 + tid] = sn[2 * tid] + sn[2 * tid + 1];
        __syncthreads();
    }

    // ---- gram ----
    const int c2 = tid >> 3;
    const int d4 = tid & 7;
    float acc[2][4];
#pragma unroll
    for (int r = 0; r < 2; r++)
#pragma unroll
        for (int i = 0; i < 4; i++) acc[r][i] = 0.f;

    for (int t0 = 0; t0 < CHUNKLEN; t0 += 64) {
#pragma unroll
        for (int rep = 0; rep < 4; rep++) {
            int lin4 = rep * 128 + tid;
            int row = lin4 >> 4;
            int col = (lin4 & 15) * 4;
            float4 v = *reinterpret_cast<const float4*>(qb + (long)row * NPIX + t0 + col);
            qs[row][col] = v.x; qs[row][col+1] = v.y; qs[row][col+2] = v.z; qs[row][col+3] = v.w;
            float4 u = *reinterpret_cast<const float4*>(kb + (long)row * NPIX + t0 + col);
            ks[row][col] = u.x; ks[row][col+1] = u.y; ks[row][col+2] = u.z; ks[row][col+3] = u.w;
        }
        __syncthreads();

#pragma unroll 8
        for (int nn = 0; nn < 64; nn++) {
            float q0 = qs[2 * c2][nn];
            float q1 = qs[2 * c2 + 1][nn];
#pragma unroll
            for (int i = 0; i < 4; i++) {
                float kv = ks[d4 * 4 + i][nn];
                acc[0][i] = fmaf(q0, kv, acc[0][i]);
                acc[1][i] = fmaf(q1, kv, acc[1][i]);
            }
        }
        __syncthreads();
    }

    float* sp = Sp + ((long)bh * NCHUNK + chunk) * 1024;
#pragma unroll
    for (int r = 0; r < 2; r++)
#pragma unroll
        for (int i = 0; i < 4; i++)
            sp[(2 * c2 + r) * 32 + (d4 * 4 + i)] = acc[r][i];
}

// ---------------- reduce + softmax + fold attention into projection ----
__global__ void softmax_fold(const float* __restrict__ Sp,
                             const float* __restrict__ np,
                             const float* __restrict__ P,
                             float* __restrict__ Mout)
{
    const int bh = blockIdx.x;
    const int b  = bh >> 3;
    const int hh = bh & 7;
    const int tid = threadIdx.x;

    __shared__ float sS[1024];
    __shared__ float qn[32], kn[32];

    for (int e = tid; e < 1024; e += 128) {
        float s = 0.f;
        for (int j = 0; j < NCHUNK; j++) s += Sp[((long)bh * NCHUNK + j) * 1024 + e];
        sS[e] = s;
    }
    if (tid < 64) {
        float s = 0.f;
        for (int j = 0; j < NCHUNK; j++) s += np[((long)bh * NCHUNK + j) * 64 + tid];
        float nv = fmaxf(sqrtf(s), 1e-12f);
        if (tid < 32) qn[tid] = nv; else kn[tid - 32] = nv;
    }
    __syncthreads();

    const float scale = 0.25f;
    if (tid < 32) {
        const int c = tid;
        float inv_q = 1.f / qn[c];
        float vals[32];
        float mx = -1e30f;
#pragma unroll
        for (int d = 0; d < 32; d++) {
            float v = sS[c * 32 + d] * scale * inv_q / kn[d];
            vals[d] = v;
            mx = fmaxf(mx, v);
        }
        float sum = 0.f;
#pragma unroll
        for (int d = 0; d < 32; d++) { vals[d] = expf(vals[d] - mx); sum += vals[d]; }
        float inv = 1.f / sum;
#pragma unroll
        for (int d = 0; d < 32; d++) sS[c * 32 + d] = vals[d] * inv;
    }
    __syncthreads();

    float prow[32];
#pragma unroll
    for (int c = 0; c < 32; c++) prow[c] = P[tid * D2 + hh * 32 + c];
#pragma unroll 4
    for (int d = 0; d < 32; d++) {
        float a = 0.f;
#pragma unroll
        for (int c = 0; c < 32; c++) a = fmaf(prow[c], sS[c * 32 + d], a);
        Mout[((long)b * 128 + tid) * D2 + hh * 32 + d] = a;
    }
}

// ---------------- launch ----------------
extern "C" void kernel_launch(void* const* d_in, const int* in_sizes, int n_in,
                              void* d_out, int out_size)
{
    const float* x[3]  = { (const float*)d_in[0], (const float*)d_in[1], (const float*)d_in[2] };
    const float* w1[3] = { (const float*)d_in[3], (const float*)d_in[5], (const float*)d_in[7] };
    const float* b1[3] = { (const float*)d_in[4], (const float*)d_in[6], (const float*)d_in[8] };
    const float* wd[3] = { (const float*)d_in[9], (const float*)d_in[11], (const float*)d_in[13] };
    const float* bd[3] = { (const float*)d_in[10], (const float*)d_in[12], (const float*)d_in[14] };
    const float* pw = (const float*)d_in[15];
    const float* pb = (const float*)d_in[16];
    float* out = (float*)d_out;

    float *t_ptr, *qkv_ptr, *Sp_ptr, *np_ptr, *M_ptr;
    cudaGetSymbolAddress((void**)&t_ptr,   g_t);
    cudaGetSymbolAddress((void**)&qkv_ptr, g_qkv);
    cudaGetSymbolAddress((void**)&Sp_ptr,  g_Sp);
    cudaGetSymbolAddress((void**)&np_ptr,  g_np);
    cudaGetSymbolAddress((void**)&M_ptr,   g_M);

    // allow >48K dynamic smem for the pipelined GEMM (attribute set, not an alloc)
    cudaFuncSetAttribute(gemm_tf32_bias,
                         cudaFuncAttributeMaxDynamicSharedMemorySize, SMEM_GEMM);

    const long planeStride = (long)D2 * NPIX;
    const long streamStride = (long)B * planeStride;

    // 1) three pointwise convs: [256x128] @ [128x16384] per batch (tf32)
    {
        dim3 grid(NPIX / 128, D2 / 128, B);
        for (int s = 0; s < 3; s++) {
            gemm_tf32_bias<<<grid, 256, SMEM_GEMM>>>(w1[s], 0,
                                          x[s], (long)CIN * NPIX,
                                          t_ptr + s * streamStride, planeStride,
                                          b1[s], D2, CIN, NPIX);
        }
    }
    // 2) depthwise 3x3 — all three streams in one launch
    {
        dim3 grid(1, HH / DWROWS, 3 * B * D2);
        dwconv3x3_v3<<<grid, 256>>>(t_ptr, qkv_ptr,
                                    wd[0], bd[0], wd[1], bd[1], wd[2], bd[2]);
    }
    // 3) gram partials
    {
        dim3 grid(NCHUNK, 64);
        gram_partial<<<grid, 128>>>(qkv_ptr + 0 * streamStride,
                                    qkv_ptr + 1 * streamStride,
                                    Sp_ptr, np_ptr);
    }
    // 4) softmax + fold
    softmax_fold<<<64, 128>>>(Sp_ptr, np_ptr, pw, M_ptr);

    // 5) final: out[b] = M[b](128x256) @ v[b](256x16384) + pb (tf32)
    {
        dim3 grid(NPIX / 128, 1, B);
        gemm_tf32_bias<<<grid, 256, SMEM_GEMM>>>(M_ptr, (long)128 * D2,
                                      qkv_ptr + 2 * streamStride, planeStride,
                                      out, (long)CIN * NPIX,
                                      pb, 128, D2, NPIX);
    }
}

// round 7
// speedup vs baseline: 3.3467x; 1.6745x over previous
#include <cuda_runtime.h>
#include <cuda_fp16.h>
#include <math.h>

// Problem constants
#define B 8
#define CIN 128
#define D2 256
#define HH 128
#define WW 128
#define NPIX (HH*WW)          // 16384
#define HEADS 8
#define CH 32                  // D2/HEADS
#define GCH 8                  // gram chunks
#define GCHLEN (NPIX/GCH)      // 2048

// ---------------- scratch (device globals; no allocation) ----------------
__device__ __half g_t[3ull*B*D2*NPIX];    // conv1x1 outputs, fp16
__device__ float  g_qkv[3ull*B*D2*NPIX];  // post-depthwise q,k,v (fp32)
__device__ float  g_Sp[64*GCH*1024];      // gram partials [bh][chunk][32*32]
__device__ float  g_np2[2*2048*4];        // sq-sum partials [stream*2048+plane][4]
__device__ float  g_M[B*128*D2];          // folded projection weights [b][128][256]

// ---------------- cp.async helpers ----------------
__device__ __forceinline__ unsigned smem_u32(const void* p) {
    unsigned a;
    asm("{ .reg .u64 t; cvta.to.shared.u64 t, %1; cvt.u32.u64 %0, t; }" : "=r"(a) : "l"(p));
    return a;
}
#define CP_ASYNC8(dst, src)  asm volatile("cp.async.ca.shared.global [%0], [%1], 8;\n"  :: "r"(dst), "l"(src))
#define CP_ASYNC16(dst, src) asm volatile("cp.async.cg.shared.global [%0], [%1], 16;\n" :: "r"(dst), "l"(src))
#define CP_COMMIT()          asm volatile("cp.async.commit_group;\n")
#define CP_WAIT1()           asm volatile("cp.async.wait_group 1;\n")
#define CP_WAIT0()           asm volatile("cp.async.wait_group 0;\n")

#define MMA_TF32(d0,d1,d2,d3,a0,a1,a2,a3,b0,b1) \
    asm volatile("mma.sync.aligned.m16n8k8.row.col.f32.tf32.tf32.f32 " \
        "{%0,%1,%2,%3}, {%4,%5,%6,%7}, {%8,%9}, {%0,%1,%2,%3};\n" \
        : "+f"(d0), "+f"(d1), "+f"(d2), "+f"(d3) \
        : "r"(a0), "r"(a1), "r"(a2), "r"(a3), "r"(b0), "r"(b1))

// =====================================================================
// tf32 GEMM + bias, cp.async double-buffered, dynamic smem, templated
// output type. z = s*8 + b : A = A{s} + b*sA, B = B{s} + b*sB,
// bias = bias{s}, C = Cbase + z*sC. Block tile 128x128, K-tile 32.
// =====================================================================
#define GK 32
#define AS_STRIDE 36
#define BS_STRIDE 136
#define AS_STAGE (128 * AS_STRIDE)
#define BS_STAGE (GK * BS_STRIDE)
#define SMEM_GEMM ((2 * AS_STAGE + 2 * BS_STAGE) * 4)  // 71680 bytes

template<typename OutT>
__global__ __launch_bounds__(256)
void gemm_tf32_bias(const float* __restrict__ A0, const float* __restrict__ A1,
                    const float* __restrict__ A2, long sA,
                    const float* __restrict__ B0, const float* __restrict__ B1,
                    const float* __restrict__ B2, long sB,
                    OutT* __restrict__ C, long sC,
                    const float* __restrict__ bias0, const float* __restrict__ bias1,
                    const float* __restrict__ bias2,
                    int M, int K, int N)
{
    extern __shared__ float dynsm[];
    float* AsBase = dynsm;
    float* BsBase = dynsm + 2 * AS_STAGE;

    const int z = blockIdx.z;
    const int s = z >> 3;
    const int bloc = z & 7;
    const float* A    = ((s == 0) ? A0 : (s == 1) ? A1 : A2) + bloc * sA;
    const float* Bm   = ((s == 0) ? B0 : (s == 1) ? B1 : B2) + bloc * sB;
    const float* bias = (s == 0) ? bias0 : (s == 1) ? bias1 : bias2;
    C += (long)z * sC;

    const int m0 = blockIdx.y * 128;
    const int n0 = blockIdx.x * 128;

    const int tid  = threadIdx.x;
    const int wid  = tid >> 5;
    const int lane = tid & 31;
    const int wm0 = (wid >> 2) * 64;
    const int wn0 = (wid & 3) * 32;
    const int r = lane >> 2;
    const int c = lane & 3;

    float acc[4][4][4];
#pragma unroll
    for (int mt = 0; mt < 4; mt++)
#pragma unroll
        for (int nt = 0; nt < 4; nt++)
#pragma unroll
            for (int i = 0; i < 4; i++) acc[mt][nt][i] = 0.f;

    const int nIter = K / GK;

    auto issue = [&](int t) {
        const int st = t & 1;
        const int k0 = t * GK;
        float* As = AsBase + st * AS_STAGE;
        float* Bs = BsBase + st * BS_STAGE;
#pragma unroll
        for (int it = 0; it < 8; it++) {
            int lin = it * 256 + tid;
            int row = lin >> 4;
            int c2  = (lin & 15) * 2;
            CP_ASYNC8(smem_u32(As + row * AS_STRIDE + c2),
                      A + (long)(m0 + row) * K + k0 + c2);
        }
#pragma unroll
        for (int it = 0; it < 4; it++) {
            int lin = it * 256 + tid;
            int row = lin >> 5;
            int c4  = (lin & 31) * 4;
            CP_ASYNC16(smem_u32(Bs + row * BS_STRIDE + c4),
                       Bm + (long)(k0 + row) * N + n0 + c4);
        }
    };

    issue(0);
    CP_COMMIT();

    for (int t = 0; t < nIter; t++) {
        if (t + 1 < nIter) { issue(t + 1); CP_COMMIT(); CP_WAIT1(); }
        else               { CP_WAIT0(); }
        __syncthreads();

        const int st = t & 1;
        const float* As = AsBase + st * AS_STAGE;
        const float* Bs = BsBase + st * BS_STAGE;
#pragma unroll
        for (int ks = 0; ks < GK; ks += 8) {
            unsigned af[4][4], bf[4][2];
#pragma unroll
            for (int mt = 0; mt < 4; mt++) {
                int mr = wm0 + mt * 16 + r;
                af[mt][0] = __float_as_uint(As[(mr    ) * AS_STRIDE + ks + c    ]);
                af[mt][1] = __float_as_uint(As[(mr + 8) * AS_STRIDE + ks + c    ]);
                af[mt][2] = __float_as_uint(As[(mr    ) * AS_STRIDE + ks + c + 4]);
                af[mt][3] = __float_as_uint(As[(mr + 8) * AS_STRIDE + ks + c + 4]);
            }
#pragma unroll
            for (int nt = 0; nt < 4; nt++) {
                int nc = wn0 + nt * 8 + r;
                bf[nt][0] = __float_as_uint(Bs[(ks + c    ) * BS_STRIDE + nc]);
                bf[nt][1] = __float_as_uint(Bs[(ks + c + 4) * BS_STRIDE + nc]);
            }
#pragma unroll
            for (int mt = 0; mt < 4; mt++)
#pragma unroll
                for (int nt = 0; nt < 4; nt++)
                    MMA_TF32(acc[mt][nt][0], acc[mt][nt][1], acc[mt][nt][2], acc[mt][nt][3],
                             af[mt][0], af[mt][1], af[mt][2], af[mt][3],
                             bf[nt][0], bf[nt][1]);
        }
        __syncthreads();
    }

#pragma unroll
    for (int mt = 0; mt < 4; mt++) {
        int row0 = m0 + wm0 + mt * 16 + r;
        float bv0 = bias[row0];
        float bv8 = bias[row0 + 8];
#pragma unroll
        for (int nt = 0; nt < 4; nt++) {
            int col = n0 + wn0 + nt * 8 + 2 * c;
            if constexpr (sizeof(OutT) == 2) {
                __half2 h0 = __floats2half2_rn(acc[mt][nt][0] + bv0, acc[mt][nt][1] + bv0);
                __half2 h8 = __floats2half2_rn(acc[mt][nt][2] + bv8, acc[mt][nt][3] + bv8);
                *reinterpret_cast<__half2*>((__half*)C + (long)row0 * N + col)       = h0;
                *reinterpret_cast<__half2*>((__half*)C + (long)(row0 + 8) * N + col) = h8;
            } else {
                float2 v0 = { acc[mt][nt][0] + bv0, acc[mt][nt][1] + bv0 };
                float2 v8 = { acc[mt][nt][2] + bv8, acc[mt][nt][3] + bv8 };
                *reinterpret_cast<float2*>((float*)C + (long)row0 * N + col)       = v0;
                *reinterpret_cast<float2*>((float*)C + (long)(row0 + 8) * N + col) = v8;
            }
        }
    }
}

// =====================================================================
// depthwise 3x3 SAME — register/shuffle version, no smem for data.
// fp16 input, fp32 output. Warp = 4 rows of one plane; lane L = cols 4L..4L+3.
// Also accumulates per-(plane, rowgroup) sum of squares for q/k norms.
// grid: (4, 3*B*D2), block 256 (8 warps x 4 rows = 32 rows)
// =====================================================================
__global__ __launch_bounds__(256)
void dwconv3x3_v4(const __half* __restrict__ in,
                  float* __restrict__ out,
                  const float* __restrict__ w0, const float* __restrict__ b0,
                  const float* __restrict__ w1, const float* __restrict__ b1,
                  const float* __restrict__ w2, const float* __restrict__ b2,
                  float* __restrict__ np2)
{
    const int z = blockIdx.y;                 // s*2048 + b*256 + oc
    const int s = z >> 11;
    const int oc = z & (D2 - 1);
    const float* wsel = (s == 0) ? w0 : (s == 1) ? w1 : w2;
    const float* bsel = (s == 0) ? b0 : (s == 1) ? b1 : b2;

    float w9[9];
#pragma unroll
    for (int t = 0; t < 9; t++) w9[t] = wsel[oc * 9 + t];
    const float bv = bsel[oc];

    const __half* ip = in + (long)z * NPIX;
    float* op = out + (long)z * NPIX;

    const int tid  = threadIdx.x;
    const int warp = tid >> 5;
    const int lane = tid & 31;
    const int row0 = blockIdx.x * 32 + warp * 4;

    auto loadwin = [&](int gr, float* w6) {
        if (gr < 0 || gr >= HH) {             // uniform across warp
#pragma unroll
            for (int j = 0; j < 6; j++) w6[j] = 0.f;
            return;
        }
        uint2 u = *reinterpret_cast<const uint2*>(ip + gr * WW + lane * 4);
        float2 f0 = __half22float2(*reinterpret_cast<__half2*>(&u.x));
        float2 f1 = __half22float2(*reinterpret_cast<__half2*>(&u.y));
        float left  = __shfl_up_sync(0xffffffffu, f1.y, 1);
        float right = __shfl_down_sync(0xffffffffu, f0.x, 1);
        if (lane == 0)  left  = 0.f;
        if (lane == 31) right = 0.f;
        w6[0] = left; w6[1] = f0.x; w6[2] = f0.y; w6[3] = f1.x; w6[4] = f1.y; w6[5] = right;
    };

    float wa[6], wb[6], wc[6];
    loadwin(row0 - 1, wa);
    loadwin(row0,     wb);

    float sq = 0.f;
#pragma unroll
    for (int i = 0; i < 4; i++) {
        loadwin(row0 + 1 + i, wc);
        float4 o;
        float* po = &o.x;
#pragma unroll
        for (int j = 0; j < 4; j++) {
            float a = bv;
#pragma unroll
            for (int dx = 0; dx < 3; dx++) {
                a = fmaf(wa[j + dx], w9[dx],     a);
                a = fmaf(wb[j + dx], w9[3 + dx], a);
                a = fmaf(wc[j + dx], w9[6 + dx], a);
            }
            po[j] = a;
            sq = fmaf(a, a, sq);
        }
        *reinterpret_cast<float4*>(op + (row0 + i) * WW + lane * 4) = o;
#pragma unroll
        for (int j = 0; j < 6; j++) { wa[j] = wb[j]; wb[j] = wc[j]; }
    }

    // block-reduce sum of squares (for q/k norm; streams 0,1 only)
#pragma unroll
    for (int off = 16; off > 0; off >>= 1)
        sq += __shfl_xor_sync(0xffffffffu, sq, off);
    __shared__ float wsum[8];
    if (lane == 0) wsum[warp] = sq;
    __syncthreads();
    if (tid == 0 && z < 2 * B * D2) {
        float t = 0.f;
#pragma unroll
        for (int w = 0; w < 8; w++) t += wsum[w];
        np2[z * 4 + blockIdx.x] = t;
    }
}

// =====================================================================
// Gram via tf32 mma: S[c][d] += q[c][px] * k[d][px] over a 2048-px chunk.
// grid (GCH, 64), block 256 (8 warps). Tile 32x64 px in smem; warp j takes
// px-slice 8j..8j+8. Cross-warp reduction through smem at the end.
// =====================================================================
__global__ __launch_bounds__(256)
void gram_mma(const float* __restrict__ qg,
              const float* __restrict__ kg,
              float* __restrict__ Sp)
{
    const int bh = blockIdx.y;
    const int chunk = blockIdx.x;
    const float* qb = qg + (long)bh * CH * NPIX + chunk * GCHLEN;
    const float* kb = kg + (long)bh * CH * NPIX + chunk * GCHLEN;

    __shared__ __align__(16) char gsm[8 * 1024 * 4];   // 32KB: tiles (17KB) then partials
    float* qs = reinterpret_cast<float*>(gsm);          // [32][68]
    float* ks = qs + 32 * 68;                           // [32][68]

    const int tid  = threadIdx.x;
    const int wid  = tid >> 5;
    const int lane = tid & 31;
    const int r = lane >> 2;
    const int c = lane & 3;
    const int px = wid * 8;      // this warp's k-slice within the 64-px tile

    float acc[2][4][4];
#pragma unroll
    for (int mt = 0; mt < 2; mt++)
#pragma unroll
        for (int nt = 0; nt < 4; nt++)
#pragma unroll
            for (int i = 0; i < 4; i++) acc[mt][nt][i] = 0.f;

    for (int t0 = 0; t0 < GCHLEN; t0 += 64) {
#pragma unroll
        for (int it = 0; it < 2; it++) {
            int lin = it * 256 + tid;
            int row = lin >> 4;
            int c4  = (lin & 15) * 4;
            CP_ASYNC16(smem_u32(qs + row * 68 + c4), qb + (long)row * NPIX + t0 + c4);
            CP_ASYNC16(smem_u32(ks + row * 68 + c4), kb + (long)row * NPIX + t0 + c4);
        }
        CP_COMMIT();
        CP_WAIT0();
        __syncthreads();

        unsigned af[2][4], bf[4][2];
#pragma unroll
        for (int mt = 0; mt < 2; mt++) {
            int mr = mt * 16 + r;
            af[mt][0] = __float_as_uint(qs[(mr    ) * 68 + px + c    ]);
            af[mt][1] = __float_as_uint(qs[(mr + 8) * 68 + px + c    ]);
            af[mt][2] = __float_as_uint(qs[(mr    ) * 68 + px + c + 4]);
            af[mt][3] = __float_as_uint(qs[(mr + 8) * 68 + px + c + 4]);
        }
#pragma unroll
        for (int nt = 0; nt < 4; nt++) {
            int nc = nt * 8 + r;
            bf[nt][0] = __float_as_uint(ks[nc * 68 + px + c    ]);
            bf[nt][1] = __float_as_uint(ks[nc * 68 + px + c + 4]);
        }
#pragma unroll
        for (int mt = 0; mt < 2; mt++)
#pragma unroll
            for (int nt = 0; nt < 4; nt++)
                MMA_TF32(acc[mt][nt][0], acc[mt][nt][1], acc[mt][nt][2], acc[mt][nt][3],
                         af[mt][0], af[mt][1], af[mt][2], af[mt][3],
                         bf[nt][0], bf[nt][1]);
        __syncthreads();
    }

    // cross-warp reduce: write each warp's 32x32 partial to smem, sum 8-way
    float* part = reinterpret_cast<float*>(gsm);        // [8][1024]
#pragma unroll
    for (int mt = 0; mt < 2; mt++) {
        int m = mt * 16 + r;
#pragma unroll
        for (int nt = 0; nt < 4; nt++) {
            int n = nt * 8 + 2 * c;
            part[wid * 1024 + m * 32 + n]           = acc[mt][nt][0];
            part[wid * 1024 + m * 32 + n + 1]       = acc[mt][nt][1];
            part[wid * 1024 + (m + 8) * 32 + n]     = acc[mt][nt][2];
            part[wid * 1024 + (m + 8) * 32 + n + 1] = acc[mt][nt][3];
        }
    }
    __syncthreads();

    const int e = tid * 4;
    float4 ssum = *reinterpret_cast<float4*>(&part[e]);
#pragma unroll
    for (int w = 1; w < 8; w++) {
        float4 v = *reinterpret_cast<float4*>(&part[w * 1024 + e]);
        ssum.x += v.x; ssum.y += v.y; ssum.z += v.z; ssum.w += v.w;
    }
    *reinterpret_cast<float4*>(&Sp[((long)bh * GCH + chunk) * 1024 + e]) = ssum;
}

// ---------------- reduce + softmax + fold attention into projection ----
__global__ void softmax_fold(const float* __restrict__ Sp,
                             const float* __restrict__ np2,
                             const float* __restrict__ P,
                             float* __restrict__ Mout)
{
    const int bh = blockIdx.x;
    const int b  = bh >> 3;
    const int hh = bh & 7;
    const int tid = threadIdx.x;

    __shared__ float sS[1024];
    __shared__ float qn[32], kn[32];

    for (int e = tid; e < 1024; e += 128) {
        float s = 0.f;
        for (int j = 0; j < GCH; j++) s += Sp[((long)bh * GCH + j) * 1024 + e];
        sS[e] = s;
    }
    if (tid < 64) {
        int ch = tid & 31;
        int zz = ((tid < 32) ? 0 : 2048) + b * 256 + hh * 32 + ch;
        float s = 0.f;
#pragma unroll
        for (int j = 0; j < 4; j++) s += np2[zz * 4 + j];
        float nv = fmaxf(sqrtf(s), 1e-12f);
        if (tid < 32) qn[ch] = nv; else kn[ch] = nv;
    }
    __syncthreads();

    const float scale = 0.25f;   // 1/sqrt(128/8)
    if (tid < 32) {
        const int c = tid;
        float inv_q = 1.f / qn[c];
        float vals[32];
        float mx = -1e30f;
#pragma unroll
        for (int d = 0; d < 32; d++) {
            float v = sS[c * 32 + d] * scale * inv_q / kn[d];
            vals[d] = v;
            mx = fmaxf(mx, v);
        }
        float sum = 0.f;
#pragma unroll
        for (int d = 0; d < 32; d++) { vals[d] = expf(vals[d] - mx); sum += vals[d]; }
        float inv = 1.f / sum;
#pragma unroll
        for (int d = 0; d < 32; d++) sS[c * 32 + d] = vals[d] * inv;
    }
    __syncthreads();

    float prow[32];
#pragma unroll
    for (int c = 0; c < 32; c++) prow[c] = P[tid * D2 + hh * 32 + c];
#pragma unroll 4
    for (int d = 0; d < 32; d++) {
        float a = 0.f;
#pragma unroll
        for (int c = 0; c < 32; c++) a = fmaf(prow[c], sS[c * 32 + d], a);
        Mout[((long)b * 128 + tid) * D2 + hh * 32 + d] = a;
    }
}

// ---------------- launch ----------------
extern "C" void kernel_launch(void* const* d_in, const int* in_sizes, int n_in,
                              void* d_out, int out_size)
{
    const float* x[3]  = { (const float*)d_in[0], (const float*)d_in[1], (const float*)d_in[2] };
    const float* w1[3] = { (const float*)d_in[3], (const float*)d_in[5], (const float*)d_in[7] };
    const float* b1[3] = { (const float*)d_in[4], (const float*)d_in[6], (const float*)d_in[8] };
    const float* wd[3] = { (const float*)d_in[9], (const float*)d_in[11], (const float*)d_in[13] };
    const float* bd[3] = { (const float*)d_in[10], (const float*)d_in[12], (const float*)d_in[14] };
    const float* pw = (const float*)d_in[15];
    const float* pb = (const float*)d_in[16];
    float* out = (float*)d_out;

    __half *t_ptr;
    float *qkv_ptr, *Sp_ptr, *np2_ptr, *M_ptr;
    cudaGetSymbolAddress((void**)&t_ptr,   g_t);
    cudaGetSymbolAddress((void**)&qkv_ptr, g_qkv);
    cudaGetSymbolAddress((void**)&Sp_ptr,  g_Sp);
    cudaGetSymbolAddress((void**)&np2_ptr, g_np2);
    cudaGetSymbolAddress((void**)&M_ptr,   g_M);

    cudaFuncSetAttribute(gemm_tf32_bias<__half>,
                         cudaFuncAttributeMaxDynamicSharedMemorySize, SMEM_GEMM);
    cudaFuncSetAttribute(gemm_tf32_bias<float>,
                         cudaFuncAttributeMaxDynamicSharedMemorySize, SMEM_GEMM);

    const long planeStride = (long)D2 * NPIX;
    const long streamStride = (long)B * planeStride;

    // 1) three pointwise convs merged: z = s*8 + b, fp16 output
    {
        dim3 grid(NPIX / 128, D2 / 128, 24);
        gemm_tf32_bias<__half><<<grid, 256, SMEM_GEMM>>>(
            w1[0], w1[1], w1[2], 0,
            x[0], x[1], x[2], (long)CIN * NPIX,
            t_ptr, planeStride,
            b1[0], b1[1], b1[2],
            D2, CIN, NPIX);
    }
    // 2) depthwise 3x3 (fp16 in, fp32 out) + norm partials
    {
        dim3 grid(4, 3 * B * D2);
        dwconv3x3_v4<<<grid, 256>>>(t_ptr, qkv_ptr,
                                    wd[0], bd[0], wd[1], bd[1], wd[2], bd[2],
                                    np2_ptr);
    }
    // 3) gram via tensor cores
    {
        dim3 grid(GCH, 64);
        gram_mma<<<grid, 256>>>(qkv_ptr + 0 * streamStride,
                                qkv_ptr + 1 * streamStride,
                                Sp_ptr);
    }
    // 4) softmax + fold attention into projection weights
    softmax_fold<<<64, 128>>>(Sp_ptr, np2_ptr, pw, M_ptr);

    // 5) final: out[b] = M[b](128x256) @ v[b](256x16384) + pb
    {
        dim3 grid(NPIX / 128, 1, 8);
        gemm_tf32_bias<float><<<grid, 256, SMEM_GEMM>>>(
            M_ptr, M_ptr, M_ptr, (long)128 * D2,
            qkv_ptr + 2 * streamStride, qkv_ptr + 2 * streamStride,
            qkv_ptr + 2 * streamStride, planeStride,
            out, (long)CIN * NPIX,
            pb, pb, pb,
            128, D2, NPIX);
    }
}